// round 1
// baseline (speedup 1.0000x reference)
#include <cuda_runtime.h>
#include <cuda_bf16.h>
#include <cstdint>

// Problem constants (fixed by setup_inputs)
#define G   128          // num graphs
#define NN  512          // nodes per graph
#define D   256          // latent dim
#define BT  128          // output tile (BT x BT)
#define KT  16           // K chunk
#define PAD 4            // smem row padding (floats)

__device__ __forceinline__ float sigmoidf_(float x) {
    // 1/(1+exp(-x)); __expf saturates to inf/0 at extremes which yields exact 0/1.
    return 1.0f / (1.0f + __expf(-x));
}

// Upper-triangular tile-pair lookup for the 4x4 tile grid (10 pairs incl. diagonal)
__constant__ int c_bi[10] = {0,0,0,0,1,1,1,2,2,3};
__constant__ int c_bj[10] = {0,1,2,3,1,2,3,2,3,3};

__global__ __launch_bounds__(256, 2)
void decoder_gemm_kernel(const float* __restrict__ z, float* __restrict__ out) {
    const int bx   = blockIdx.x;
    const int g    = bx / 10;
    const int pair = bx - g * 10;
    const int bi   = c_bi[pair];
    const int bj   = c_bj[pair];

    __shared__ float As[KT][BT + PAD];
    __shared__ float Bs[KT][BT + PAD];

    const int tid = threadIdx.x;
    const int tx  = tid & 15;         // 0..15  -> column group
    const int ty  = tid >> 4;         // 0..15  -> row group
    const int row0 = ty * 8;          // within-tile row base
    const int col0 = tx * 8;          // within-tile col base

    // Global bases for this graph's A and B row blocks
    const float* Ab = z + ((size_t)g * NN + (size_t)bi * BT) * D;
    const float* Bb = z + ((size_t)g * NN + (size_t)bj * BT) * D;

    float acc[8][8];
    #pragma unroll
    for (int i = 0; i < 8; ++i)
        #pragma unroll
        for (int j = 0; j < 8; ++j) acc[i][j] = 0.0f;

    // K loop
    for (int k0 = 0; k0 < D; k0 += KT) {
        // Cooperative tile load: 128 rows x 16 cols = 512 float4; 256 threads x 2.
        #pragma unroll
        for (int s = 0; s < 2; ++s) {
            int f   = tid * 2 + s;        // float4 index, 4 per row
            int row = f >> 2;
            int kq  = f & 3;              // which float4 within the 16-wide chunk
            float4 av = *reinterpret_cast<const float4*>(Ab + (size_t)row * D + k0 + kq * 4);
            float4 bv = *reinterpret_cast<const float4*>(Bb + (size_t)row * D + k0 + kq * 4);
            int kk = kq * 4;
            As[kk + 0][row] = av.x; As[kk + 1][row] = av.y;
            As[kk + 2][row] = av.z; As[kk + 3][row] = av.w;
            Bs[kk + 0][row] = bv.x; Bs[kk + 1][row] = bv.y;
            Bs[kk + 2][row] = bv.z; Bs[kk + 3][row] = bv.w;
        }
        __syncthreads();

        #pragma unroll
        for (int kk = 0; kk < KT; ++kk) {
            float4 a0 = *reinterpret_cast<const float4*>(&As[kk][row0]);
            float4 a1 = *reinterpret_cast<const float4*>(&As[kk][row0 + 4]);
            float4 b0 = *reinterpret_cast<const float4*>(&Bs[kk][col0]);
            float4 b1 = *reinterpret_cast<const float4*>(&Bs[kk][col0 + 4]);
            float ar[8] = {a0.x, a0.y, a0.z, a0.w, a1.x, a1.y, a1.z, a1.w};
            float br[8] = {b0.x, b0.y, b0.z, b0.w, b1.x, b1.y, b1.z, b1.w};
            #pragma unroll
            for (int i = 0; i < 8; ++i)
                #pragma unroll
                for (int j = 0; j < 8; ++j)
                    acc[i][j] = fmaf(ar[i], br[j], acc[i][j]);
        }
        __syncthreads();
    }

    // Epilogue: sigmoid + store tile (and mirrored tile when off-diagonal)
    float* outg = out + (size_t)g * NN * NN;

    #pragma unroll
    for (int i = 0; i < 8; ++i) {
        int r = bi * BT + row0 + i;
        float4 v0, v1;
        v0.x = sigmoidf_(acc[i][0]); v0.y = sigmoidf_(acc[i][1]);
        v0.z = sigmoidf_(acc[i][2]); v0.w = sigmoidf_(acc[i][3]);
        v1.x = sigmoidf_(acc[i][4]); v1.y = sigmoidf_(acc[i][5]);
        v1.z = sigmoidf_(acc[i][6]); v1.w = sigmoidf_(acc[i][7]);
        float* p = outg + (size_t)r * NN + bj * BT + col0;
        *reinterpret_cast<float4*>(p)     = v0;
        *reinterpret_cast<float4*>(p + 4) = v1;
    }

    if (bi != bj) {
        #pragma unroll
        for (int j = 0; j < 8; ++j) {
            int c = bj * BT + col0 + j;
            float4 v0, v1;
            v0.x = sigmoidf_(acc[0][j]); v0.y = sigmoidf_(acc[1][j]);
            v0.z = sigmoidf_(acc[2][j]); v0.w = sigmoidf_(acc[3][j]);
            v1.x = sigmoidf_(acc[4][j]); v1.y = sigmoidf_(acc[5][j]);
            v1.z = sigmoidf_(acc[6][j]); v1.w = sigmoidf_(acc[7][j]);
            float* p = outg + (size_t)c * NN + bi * BT + row0;
            *reinterpret_cast<float4*>(p)     = v0;
            *reinterpret_cast<float4*>(p + 4) = v1;
        }
    }
}

extern "C" void kernel_launch(void* const* d_in, const int* in_sizes, int n_in,
                              void* d_out, int out_size) {
    const float* z = (const float*)d_in[0];
    float* out = (float*)d_out;
    // 128 graphs * 10 upper-tri tile pairs of the 4x4 tile grid
    decoder_gemm_kernel<<<G * 10, 256>>>(z, out);
}

// round 8
// speedup vs baseline: 1.9332x; 1.9332x over previous
#include <cuda_runtime.h>
#include <cuda_bf16.h>
#include <cstdint>

#define G     128
#define NN    512
#define D     256
#define BT    128
#define KTOT  512              // bf16 per row in g_zs: [hi(256) | lo(256)]
#define ROWB  (KTOT * 2)       // 1024 bytes per row
#define KC    32               // K elements per chunk
#define NCH   (D / KC)         // 8 chunks over the 256-dim half
#define NTOT  (G * NN)

// Scratch: split z into bf16 hi|lo (64 MB)
__device__ __nv_bfloat16 g_zs[(size_t)NTOT * KTOT];

__constant__ int c_bi[10] = {0,0,0,0,1,1,1,2,2,3};
__constant__ int c_bj[10] = {0,1,2,3,1,2,3,2,3,3};

#define SWZ64(o) ((o) ^ (((o) >> 3) & 0x30))

__device__ __forceinline__ uint32_t smem_u32(const void* p) {
    uint32_t a;
    asm("{ .reg .u64 t; cvta.to.shared.u64 t, %1; cvt.u32.u64 %0, t; }" : "=r"(a) : "l"(p));
    return a;
}

#define CP_ASYNC16(dst, src) \
    asm volatile("cp.async.ca.shared.global [%0], [%1], 16;" :: "r"(dst), "l"(src))
#define CP_COMMIT() asm volatile("cp.async.commit_group;" ::: "memory")
#define CP_WAIT0()  asm volatile("cp.async.wait_group 0;"  ::: "memory")

#define LDMX4(r0, r1, r2, r3, addr) \
    asm volatile("ldmatrix.sync.aligned.m8n8.x4.shared.b16 {%0,%1,%2,%3}, [%4];" \
                 : "=r"(r0), "=r"(r1), "=r"(r2), "=r"(r3) : "r"(addr))

#define MMA16816(d0, d1, d2, d3, a0, a1, a2, a3, b0, b1) \
    asm volatile("mma.sync.aligned.m16n8k16.row.col.f32.bf16.bf16.f32 " \
                 "{%0,%1,%2,%3}, {%4,%5,%6,%7}, {%8,%9}, {%0,%1,%2,%3};" \
                 : "+f"(d0), "+f"(d1), "+f"(d2), "+f"(d3) \
                 : "r"(a0), "r"(a1), "r"(a2), "r"(a3), "r"(b0), "r"(b1))

// SMEM: 2 stages x 4 buffers (A_hi, A_lo, B_hi, B_lo) x 8KB = 64 KB pipeline.
// Epilogue reuses as float tile [128][132] = 67,584 B (the max).
#define BUFSZ      8192
#define STAGE_SZ   (4 * BUFSZ)          // 32768
#define EPAD       132
#define SMEM_BYTES (BT * EPAD * 4)      // 67584

// ---------------- Phase 1: split z -> bf16 hi|lo ----------------
__global__ void split_kernel(const float* __restrict__ z) {
    size_t i = ((size_t)blockIdx.x * blockDim.x + threadIdx.x) * 4;
    if (i >= (size_t)NTOT * D) return;
    float4 v = *reinterpret_cast<const float4*>(z + i);
    float f[4] = {v.x, v.y, v.z, v.w};
    union { unsigned short s[4]; uint2 u; } hi, lo;
    #pragma unroll
    for (int k = 0; k < 4; ++k) {
        __nv_bfloat16 h = __float2bfloat16(f[k]);
        hi.s[k] = __bfloat16_as_ushort(h);
        __nv_bfloat16 l = __float2bfloat16(f[k] - __bfloat162float(h));
        lo.s[k] = __bfloat16_as_ushort(l);
    }
    size_t node = i >> 8;
    size_t kk   = i & 255;
    __nv_bfloat16* row = g_zs + node * KTOT;
    *reinterpret_cast<uint2*>(row + kk)       = hi.u;
    *reinterpret_cast<uint2*>(row + 256 + kk) = lo.u;
}

// ---------------- Phase 2: HMMA GEMM (3-term split) + sigmoid ----------------
__global__ __launch_bounds__(256, 2)
void decoder_hmma_kernel(float* __restrict__ out) {
    extern __shared__ __align__(1024) char smem[];
    const uint32_t sbase = smem_u32(smem);
    float* smemF = reinterpret_cast<float*>(smem);

    const int tid = threadIdx.x;
    const int w   = tid >> 5;
    const int l   = tid & 31;
    const int wm  = w & 3;          // 0..3: 32-row block
    const int wn  = w >> 2;         // 0..1: 64-col block

    const int bx   = blockIdx.x;
    const int g    = bx / 10;
    const int pair = bx - g * 10;
    const int bi   = c_bi[pair];
    const int bj   = c_bj[pair];
    const bool diag = (bi == bj);

    const char* gA = reinterpret_cast<const char*>(g_zs) + ((size_t)g * NN + (size_t)bi * BT) * ROWB;
    const char* gB = reinterpret_cast<const char*>(g_zs) + ((size_t)g * NN + (size_t)bj * BT) * ROWB;

    // Per chunk c (32 elems = 64B): hi half at byte c*64, lo half at 512 + c*64.
    auto prefetch = [&](int c, int stage) {
        const uint32_t st = sbase + stage * STAGE_SZ;
        const int nbuf = diag ? 2 : 4;
        #pragma unroll
        for (int which = 0; which < 4; ++which) {
            if (which >= nbuf) break;
            const char* gp   = (which < 2) ? gA : gB;
            const int   hoff = (which & 1) ? 512 : 0;
            const uint32_t dst0 = st + which * BUFSZ;
            #pragma unroll
            for (int it = 0; it < 2; ++it) {
                int f   = it * 256 + tid;     // 0..511
                int row = f >> 2;
                int q   = f & 3;
                const char* src = gp + (size_t)row * ROWB + hoff + c * 64 + q * 16;
                CP_ASYNC16(dst0 + SWZ64((uint32_t)(row * 64 + q * 16)), src);
            }
        }
        CP_COMMIT();
    };

    float acc[2][8][4];
    #pragma unroll
    for (int mi = 0; mi < 2; ++mi)
        #pragma unroll
        for (int ni = 0; ni < 8; ++ni)
            #pragma unroll
            for (int r = 0; r < 4; ++r) acc[mi][ni][r] = 0.0f;

    // ldmatrix lane-derived constants
    const int mat = l >> 3;
    const int lr  = l & 7;
    const int a_roff = (mat & 1) * 8 + lr;
    const int a_koff = (mat >> 1) * 16;
    const int b_roff = (mat >> 1) * 8 + lr;
    const int b_koff = (mat & 1) * 16;

    prefetch(0, 0);

    for (int c = 0; c < NCH; ++c) {
        const int stage = c & 1;
        CP_WAIT0();
        __syncthreads();
        if (c + 1 < NCH) prefetch(c + 1, stage ^ 1);

        const uint32_t st = sbase + stage * STAGE_SZ;
        const uint32_t A_hi = st;
        const uint32_t A_lo = st + BUFSZ;
        const uint32_t B_hi = diag ? A_hi : (st + 2 * BUFSZ);
        const uint32_t B_lo = diag ? A_lo : (st + 3 * BUFSZ);

        // 3 terms: (A_hi,B_hi), (A_hi,B_lo), (A_lo,B_hi); each 2 k16-steps
        #pragma unroll
        for (int t = 0; t < 3; ++t) {
            const uint32_t Ab = (t < 2) ? A_hi : A_lo;
            const uint32_t Bb = (t == 1) ? B_lo : B_hi;
            #pragma unroll
            for (int ks = 0; ks < 2; ++ks) {
                const int kb = ks * 32;
                uint32_t a[2][4];
                #pragma unroll
                for (int mi = 0; mi < 2; ++mi) {
                    int row = wm * 32 + mi * 16 + a_roff;
                    uint32_t addr = Ab + SWZ64((uint32_t)(row * 64 + kb + a_koff));
                    LDMX4(a[mi][0], a[mi][1], a[mi][2], a[mi][3], addr);
                }
                uint32_t b[8][2];
                #pragma unroll
                for (int np = 0; np < 4; ++np) {
                    int row = wn * 64 + np * 16 + b_roff;
                    uint32_t addr = Bb + SWZ64((uint32_t)(row * 64 + kb + b_koff));
                    LDMX4(b[np*2][0], b[np*2][1], b[np*2+1][0], b[np*2+1][1], addr);
                }
                #pragma unroll
                for (int mi = 0; mi < 2; ++mi)
                    #pragma unroll
                    for (int ni = 0; ni < 8; ++ni)
                        MMA16816(acc[mi][ni][0], acc[mi][ni][1], acc[mi][ni][2], acc[mi][ni][3],
                                 a[mi][0], a[mi][1], a[mi][2], a[mi][3],
                                 b[ni][0], b[ni][1]);
            }
        }
        __syncthreads();
    }

    // ---- Epilogue: sigmoid -> smem tile -> coalesced stores (+ mirror) ----
    const int tq  = l >> 2;
    const int tc2 = (l & 3) * 2;
    #pragma unroll
    for (int mi = 0; mi < 2; ++mi) {
        #pragma unroll
        for (int ni = 0; ni < 8; ++ni) {
            int rr = wm * 32 + mi * 16 + tq;
            int cc = wn * 64 + ni * 8 + tc2;
            float2 v0, v1;
            v0.x = __fdividef(1.0f, 1.0f + __expf(-acc[mi][ni][0]));
            v0.y = __fdividef(1.0f, 1.0f + __expf(-acc[mi][ni][1]));
            v1.x = __fdividef(1.0f, 1.0f + __expf(-acc[mi][ni][2]));
            v1.y = __fdividef(1.0f, 1.0f + __expf(-acc[mi][ni][3]));
            *reinterpret_cast<float2*>(&smemF[rr * EPAD + cc])       = v0;
            *reinterpret_cast<float2*>(&smemF[(rr + 8) * EPAD + cc]) = v1;
        }
    }
    __syncthreads();

    float* outg = out + (size_t)g * NN * NN;
    const int rbase = bi * BT;
    const int cbase = bj * BT;

    #pragma unroll
    for (int t4 = tid; t4 < BT * 32; t4 += 256) {
        int row = t4 >> 5, q = t4 & 31;
        float4 v = *reinterpret_cast<const float4*>(&smemF[row * EPAD + q * 4]);
        *reinterpret_cast<float4*>(&outg[(size_t)(rbase + row) * NN + cbase + q * 4]) = v;
    }
    if (!diag) {
        #pragma unroll
        for (int t4 = tid; t4 < BT * 32; t4 += 256) {
            int tcc = t4 >> 5, q = t4 & 31;
            float4 v;
            v.x = smemF[(q * 4 + 0) * EPAD + tcc];
            v.y = smemF[(q * 4 + 1) * EPAD + tcc];
            v.z = smemF[(q * 4 + 2) * EPAD + tcc];
            v.w = smemF[(q * 4 + 3) * EPAD + tcc];
            *reinterpret_cast<float4*>(&outg[(size_t)(cbase + tcc) * NN + rbase + q * 4]) = v;
        }
    }
}

extern "C" void kernel_launch(void* const* d_in, const int* in_sizes, int n_in,
                              void* d_out, int out_size) {
    const float* z = (const float*)d_in[0];
    float* out = (float*)d_out;

    cudaFuncSetAttribute(decoder_hmma_kernel, cudaFuncAttributeMaxDynamicSharedMemorySize, SMEM_BYTES);

    size_t nvec = ((size_t)NTOT * D) / 4;
    split_kernel<<<(int)((nvec + 255) / 256), 256>>>(z);
    decoder_hmma_kernel<<<G * 10, 256, SMEM_BYTES>>>(out);
}